// round 5
// baseline (speedup 1.0000x reference)
#include <cuda_runtime.h>

// Shape: [1, 8, 8, 8, 258, 258, 1] fp32
//   images = 512, each 258x258; total = 34,080,768 elems = 17,040,384 float2.
//
// Branchless float2 formulation (corrected from R4).
// Chunk w2 covers cols (2*w2, 2*w2+1). hadj = +258 (h==0) / -258 (h==257)
// is ALWAYS applied to the main vector load:
//     v = x[h+hadj][2*w2 .. 2*w2+1]
// Lane mapping (w-axis assigns run last, so true w-edges use ORIGINAL h):
//   interior:        a0 = v.x              a1 = v.y
//   w2==0   (w=0,1): a0 = x[h][1]  (= v.y if hadj==0, else scalar load)
//                    a1 = v.y   (= x[h+hadj][1], correct for w=1)
//   w2==128 (256,257): a0 = v.x  (= x[h+hadj][256], correct for w=256)
//                    a1 = x[h][256] (= v.x if hadj==0, else scalar load)
// Scalar loads fire for only 4 threads per image (2048 of 17M threads).

#define HW        258
#define IMG_ELEMS 66564u       // 258*258
#define ROW2      129u         // float2 chunks per row
#define IMG2      33282u       // float2 chunks per image
#define TOTAL2    17040384u
#define NBLOCKS   66564        // TOTAL2 / 256 exactly

__global__ __launch_bounds__(256)
void halo_f2_kernel(const float* __restrict__ x,
                    const float2* __restrict__ hm,
                    float2* __restrict__ out)
{
    unsigned i = blockIdx.x * 256u + threadIdx.x;   // exact cover, no tail

    float2 b = __ldcs(hm + i);

    unsigned img = i / IMG2;
    unsigned rem = i - img * IMG2;
    unsigned h   = rem / ROW2;
    unsigned w2  = rem - h * ROW2;

    bool we0 = (w2 == 0u);
    bool we1 = (w2 == ROW2 - 1u);

    int hadj = 0;
    if (h == 0u)            hadj =  HW;
    else if (h == HW - 1u)  hadj = -HW;

    unsigned rowbase = img * IMG_ELEMS + h * (unsigned)HW;

    const float2* px =
        reinterpret_cast<const float2*>(x + (int)rowbase + hadj) + w2;
    float2 v = __ldcs(px);

    float a0 = v.x;
    float a1 = v.y;
    if (we0) {
        a0 = (hadj != 0) ? __ldg(x + rowbase + 1u)   : v.y;
        // a1 = v.y already correct (x[h+hadj][1])
    }
    if (we1) {
        a1 = (hadj != 0) ? __ldg(x + rowbase + 256u) : v.x;
        // a0 = v.x already correct (x[h+hadj][256])
    }

    float2 o;
    o.x = a0 * b.x;
    o.y = a1 * b.y;
    __stcs(out + i, o);
}

extern "C" void kernel_launch(void* const* d_in, const int* in_sizes, int n_in,
                              void* d_out, int out_size)
{
    const float* x  = (const float*)d_in[0];
    const float* hm = (const float*)d_in[1];
    float* out = (float*)d_out;

    halo_f2_kernel<<<NBLOCKS, 256>>>(x, (const float2*)hm, (float2*)out);
}

// round 6
// speedup vs baseline: 1.1756x; 1.1756x over previous
#include <cuda_runtime.h>

// Shape: [1, 8, 8, 8, 258, 258, 1] fp32; total = 34,080,768 elems = 8,520,192 float4.
//
// Key fact: 258 % 4 == 2, so every w-edge element shares its 16B chunk with its
// remap source -> w-edge remap is a register permute of the already-loaded v:
//   w0==0   chunk (w 0..3):            lane0 <- v.y          (x[h][1])
//   w0==254 chunk (w 254..257):        lane3 <- v.z          (x[h][256])
//   w0==256 straddle (h:256,257 / h+1:0,1): lane1 <- v.x,  lane2 <- v.w
// Only rows h==0 / h==257 (plus the straddle into row 257 / out of row 0) need
// real extra loads; those chunks live in ~1.7% of warps -> divergent slow path
// with 4 scalar loads at idx+k+delta (delta = +-1 for w-edge, +-258 for h-edge).

#define HW        258
#define IMG_ELEMS 66564u      // 258*258
#define TOTAL4    8520192u    // total float4 chunks (TOTAL/4)

__global__ __launch_bounds__(256)
void halo_f4_kernel(const float* __restrict__ x,
                    const float4* __restrict__ hm,
                    float4* __restrict__ out)
{
    unsigned i = blockIdx.x * 256u + threadIdx.x;
    if (i >= TOTAL4) return;
    unsigned idx = i * 4u;

    float4 v = __ldcs(reinterpret_cast<const float4*>(x + idx));
    float4 b = __ldcs(hm + i);

    unsigned rem = idx % IMG_ELEMS;          // magic-mul div
    unsigned h0  = rem / HW;                 // magic-mul div
    unsigned w0  = rem - h0 * HW;            // even, 0..256

    float a0 = v.x, a1 = v.y, a2 = v.z, a3 = v.w;

    // h-edge slow path: chunk touches row 0 or row 257.
    if (h0 == 0u || h0 == HW - 1u || (h0 == HW - 2u && w0 == HW - 2u)) {
        unsigned h = h0, w = w0;
        float lane[4];
#pragma unroll
        for (int k = 0; k < 4; ++k) {
            int delta = 0;
            if (w == 0u)           delta = 1;          // w-edge: original h
            else if (w == HW - 1u) delta = -1;
            else if (h == 0u)      delta = HW;         // h-edge
            else if (h == HW - 1u) delta = -HW;
            lane[k] = __ldg(x + (int)(idx + k) + delta);
            if (++w == HW) { w = 0u; ++h; }
        }
        a0 = lane[0]; a1 = lane[1]; a2 = lane[2]; a3 = lane[3];
    } else {
        // Branchless w-edge permutes (predicated selects).
        if (w0 == 0u)           a0 = v.y;              // (h,0)   <- x[h][1]
        if (w0 == HW - 4u)      a3 = v.z;              // (h,257) <- x[h][256]
        if (w0 == HW - 2u) {                            // straddle chunk
            a1 = v.x;                                   // (h,257) <- x[h][256]
            a2 = v.w;                                   // (h+1,0) <- x[h+1][1]
        }
    }

    float4 r;
    r.x = a0 * b.x;
    r.y = a1 * b.y;
    r.z = a2 * b.z;
    r.w = a3 * b.w;
    __stcs(out + i, r);
}

extern "C" void kernel_launch(void* const* d_in, const int* in_sizes, int n_in,
                              void* d_out, int out_size)
{
    const float* x  = (const float*)d_in[0];
    const float* hm = (const float*)d_in[1];
    float* out = (float*)d_out;

    const int threads = 256;
    const int blocks = (TOTAL4 + threads - 1) / threads;  // 33,282
    halo_f4_kernel<<<blocks, threads>>>(x, (const float4*)hm, (float4*)out);
}